// round 1
// baseline (speedup 1.0000x reference)
#include <cuda_runtime.h>
#include <math.h>

// Problem constants
#define MROWS  50176          // B*L = B_*N = 16*3136
#define CDIM   384
#define HIDDEN 1536
#define NHEADS 12
#define HDIM   32
#define NWIN   49             // tokens per window
#define BWIN   1024           // number of windows (16 * 8 * 8)

// -------- scratch (device globals; no allocations allowed) --------
__device__ float g_hw [(size_t)MROWS * CDIM];    // LN1 output, window order
__device__ float g_q  [(size_t)MROWS * CDIM];    // q, (B_, NH, N, HD)
__device__ float g_ao [(size_t)MROWS * CDIM];    // attention out, (B_, N, C)
__device__ float g_x1 [(size_t)MROWS * CDIM];    // x + attn, natural (B, L, C)
__device__ float g_h2 [(size_t)MROWS * CDIM];    // LN2 output
__device__ float g_mid[(size_t)MROWS * HIDDEN];  // gelu(fc1)

// ============================================================
// LayerNorm. windowed=1: input read through window-partition
// mapping (row index is window-order), output in window order.
// windowed=0: straight rows.
// ============================================================
__global__ void ln_kernel(const float* __restrict__ xin, const float* __restrict__ g,
                          const float* __restrict__ bb, float* __restrict__ out,
                          int windowed)
{
    int r = blockIdx.x;
    size_t srow;
    if (windowed) {
        int w = r / NWIN, n = r % NWIN;
        int bimg = w >> 6, wy = (w >> 3) & 7, wx = w & 7;
        int iy = n / 7, ix = n % 7;
        int l = (wy * 7 + iy) * 56 + (wx * 7 + ix);
        srow = (size_t)bimg * 3136 + l;
    } else {
        srow = (size_t)r;
    }
    const float* xr = xin + srow * CDIM;
    int tid = threadIdx.x;                 // 128 threads
    float v0 = xr[tid], v1 = xr[tid + 128], v2 = xr[tid + 256];
    float s  = v0 + v1 + v2;
    float ss = v0 * v0 + v1 * v1 + v2 * v2;
    #pragma unroll
    for (int o = 16; o; o >>= 1) {
        s  += __shfl_xor_sync(0xffffffffu, s,  o);
        ss += __shfl_xor_sync(0xffffffffu, ss, o);
    }
    __shared__ float rs[4], rss[4];
    __shared__ float smean, sinv;
    int warp = tid >> 5, lane = tid & 31;
    if (lane == 0) { rs[warp] = s; rss[warp] = ss; }
    __syncthreads();
    if (tid == 0) {
        float S = rs[0] + rs[1] + rs[2] + rs[3];
        float SS = rss[0] + rss[1] + rss[2] + rss[3];
        float m = S * (1.0f / 384.0f);
        float var = SS * (1.0f / 384.0f) - m * m;
        smean = m;
        sinv = rsqrtf(var + 1e-5f);
    }
    __syncthreads();
    float* orow = out + (size_t)r * CDIM;
    orow[tid]       = (v0 - smean) * sinv * g[tid]       + bb[tid];
    orow[tid + 128] = (v1 - smean) * sinv * g[tid + 128] + bb[tid + 128];
    orow[tid + 256] = (v2 - smean) * sinv * g[tid + 256] + bb[tid + 256];
}

// ============================================================
// SGEMM 128x128x8, 256 threads, 8x8 microtile, fp32.
// C_raw = A(MxK, lda) @ B(KxN, ldb); epilogue per template.
// ============================================================
enum { EPI_Q = 0, EPI_PROJ = 1, EPI_GELU = 2, EPI_FC2 = 3 };

template <int EPI>
__global__ void __launch_bounds__(256)
sgemm_kernel(const float* __restrict__ A, const float* __restrict__ Bm,
             int K, int lda, int ldb, int ldc,
             const float* __restrict__ bias, float* __restrict__ C,
             const float* __restrict__ resid, float scale)
{
    __shared__ float As[8][128];
    __shared__ float Bs[8][128];

    int bm = blockIdx.y * 128;
    int bn = blockIdx.x * 128;
    int tid = threadIdx.x;

    int aRow = tid >> 1, aCol = (tid & 1) << 2;       // A tile: 128x8, one float4/thread
    int bRow = tid >> 5, bCol = (tid & 31) << 2;      // B tile: 8x128, one float4/thread
    int trow = (tid >> 4) << 3;                       // output microtile origin
    int tcol = (tid & 15) << 3;

    float acc[8][8];
    #pragma unroll
    for (int i = 0; i < 8; ++i)
        #pragma unroll
        for (int j = 0; j < 8; ++j) acc[i][j] = 0.0f;

    const float* Aptr = A + (size_t)(bm + aRow) * lda + aCol;
    const float* Bptr = Bm + (size_t)bRow * ldb + bn + bCol;

    for (int k0 = 0; k0 < K; k0 += 8) {
        float4 av = *(const float4*)(Aptr + k0);
        As[aCol + 0][aRow] = av.x;
        As[aCol + 1][aRow] = av.y;
        As[aCol + 2][aRow] = av.z;
        As[aCol + 3][aRow] = av.w;
        float4 bv = *(const float4*)(Bptr + (size_t)k0 * ldb);
        *(float4*)&Bs[bRow][bCol] = bv;
        __syncthreads();

        #pragma unroll
        for (int k = 0; k < 8; ++k) {
            float4 a0 = *(const float4*)&As[k][trow];
            float4 a1 = *(const float4*)&As[k][trow + 4];
            float4 b0 = *(const float4*)&Bs[k][tcol];
            float4 b1 = *(const float4*)&Bs[k][tcol + 4];
            float a[8] = {a0.x, a0.y, a0.z, a0.w, a1.x, a1.y, a1.z, a1.w};
            float b[8] = {b0.x, b0.y, b0.z, b0.w, b1.x, b1.y, b1.z, b1.w};
            #pragma unroll
            for (int i = 0; i < 8; ++i)
                #pragma unroll
                for (int j = 0; j < 8; ++j)
                    acc[i][j] += a[i] * b[j];
        }
        __syncthreads();
    }

    // ---------------- epilogues ----------------
    #pragma unroll
    for (int i = 0; i < 8; ++i) {
        int row = bm + trow + i;
        if (EPI == EPI_Q) {
            int w = row / NWIN, n = row % NWIN;
            #pragma unroll
            for (int j = 0; j < 8; ++j) {
                int col = bn + tcol + j;
                int hd = col >> 5, d = col & 31;
                size_t o = ((size_t)(w * NHEADS + hd) * NWIN + n) * HDIM + d;
                C[o] = (acc[i][j] + bias[col]) * scale;
            }
        } else if (EPI == EPI_PROJ) {
            int w = row / NWIN, n = row % NWIN;
            int bimg = w >> 6, wy = (w >> 3) & 7, wx = w & 7;
            int iy = n / 7, ix = n % 7;
            size_t orow = ((size_t)bimg * 3136 + (wy * 7 + iy) * 56 + (wx * 7 + ix)) * CDIM;
            #pragma unroll
            for (int j = 0; j < 8; ++j) {
                int col = bn + tcol + j;
                size_t o = orow + col;
                C[o] = acc[i][j] + bias[col] + resid[o];
            }
        } else if (EPI == EPI_GELU) {
            size_t orow = (size_t)row * ldc;
            #pragma unroll
            for (int j = 0; j < 8; ++j) {
                int col = bn + tcol + j;
                float val = acc[i][j] + bias[col];
                C[orow + col] = 0.5f * val * (1.0f + erff(val * 0.70710678118654752f));
            }
        } else { // EPI_FC2
            size_t orow = (size_t)row * ldc;
            #pragma unroll
            for (int j = 0; j < 8; ++j) {
                int col = bn + tcol + j;
                size_t o = orow + col;
                C[o] = acc[i][j] + bias[col] + resid[o];
            }
        }
    }
}

// ============================================================
// Windowed attention: one block per (window, head).
// scores = q@k^T + bias ; softmax ; out = P@v
// ============================================================
__global__ void __launch_bounds__(256)
attn_kernel(const float* __restrict__ q, const float* __restrict__ kv,
            const int* __restrict__ rel, const float* __restrict__ btab,
            float* __restrict__ ao)
{
    __shared__ float sq[NWIN * HDIM];
    __shared__ float sk[NWIN * HDIM];
    __shared__ float sv[NWIN * HDIM];
    __shared__ float sS[NWIN * 52];

    int blk = blockIdx.x;                 // w * 12 + h
    int w = blk / NHEADS, h = blk - w * NHEADS;
    int bimg = w >> 6;                    // 64 windows per image
    int tid = threadIdx.x;

    const float* qp = q + (size_t)blk * (NWIN * HDIM);
    const float* kp = kv + (size_t)(bimg * NHEADS + h) * (NWIN * HDIM);
    const float* vp = kp + (size_t)16 * NHEADS * NWIN * HDIM;  // second half of kv

    for (int t = tid; t < NWIN * HDIM; t += 256) {
        sq[t] = qp[t];
        sk[t] = kp[t];
        sv[t] = vp[t];
    }
    __syncthreads();

    // scores + relative position bias
    for (int t = tid; t < NWIN * NWIN; t += 256) {
        int i = t / NWIN, j = t - i * NWIN;
        float s = 0.0f;
        #pragma unroll
        for (int d = 0; d < HDIM; ++d) s += sq[i * HDIM + d] * sk[j * HDIM + d];
        s += btab[rel[t] * NHEADS + h];
        sS[i * 52 + j] = s;
    }
    __syncthreads();

    // softmax, one row per warp (round robin over 8 warps)
    int warp = tid >> 5, lane = tid & 31;
    for (int i = warp; i < NWIN; i += 8) {
        float v1 = sS[i * 52 + lane];
        float v2 = (lane + 32 < NWIN) ? sS[i * 52 + lane + 32] : -1e30f;
        float m = fmaxf(v1, v2);
        #pragma unroll
        for (int o = 16; o; o >>= 1) m = fmaxf(m, __shfl_xor_sync(0xffffffffu, m, o));
        float e1 = expf(v1 - m);
        float e2 = (lane + 32 < NWIN) ? expf(v2 - m) : 0.0f;
        float s = e1 + e2;
        #pragma unroll
        for (int o = 16; o; o >>= 1) s += __shfl_xor_sync(0xffffffffu, s, o);
        float inv = 1.0f / s;
        sS[i * 52 + lane] = e1 * inv;
        if (lane + 32 < NWIN) sS[i * 52 + lane + 32] = e2 * inv;
    }
    __syncthreads();

    // out = P @ v  -> (B_, N, C) with head-interleaved channels
    for (int t = tid; t < NWIN * HDIM; t += 256) {
        int i = t >> 5, d = t & 31;
        float o = 0.0f;
        #pragma unroll
        for (int j = 0; j < NWIN; ++j) o += sS[i * 52 + j] * sv[j * HDIM + d];
        ao[((size_t)w * NWIN + i) * CDIM + h * HDIM + d] = o;
    }
}

// ============================================================
// launch
// ============================================================
extern "C" void kernel_launch(void* const* d_in, const int* in_sizes, int n_in,
                              void* d_out, int out_size)
{
    (void)in_sizes; (void)n_in; (void)out_size;
    const float* x     = (const float*)d_in[0];
    const float* kv    = (const float*)d_in[1];
    const int*   rel   = (const int*)d_in[2];
    // d_in[3], d_in[4] = H, W (constants; unused)
    const float* g1    = (const float*)d_in[5];
    const float* b1    = (const float*)d_in[6];
    const float* Wqkv  = (const float*)d_in[7];
    const float* bqkv  = (const float*)d_in[8];
    const float* btab  = (const float*)d_in[9];
    const float* Wproj = (const float*)d_in[10];
    const float* bproj = (const float*)d_in[11];
    const float* g2    = (const float*)d_in[12];
    const float* b2    = (const float*)d_in[13];
    const float* Wfc1  = (const float*)d_in[14];
    const float* bfc1  = (const float*)d_in[15];
    const float* Wfc2  = (const float*)d_in[16];
    const float* bfc2  = (const float*)d_in[17];
    float* out = (float*)d_out;

    static float *hw = nullptr, *q = nullptr, *ao = nullptr,
                 *x1 = nullptr, *h2 = nullptr, *mid = nullptr;
    if (!hw) {  // resolved on the (non-captured) correctness call; cached after
        cudaGetSymbolAddress((void**)&hw,  g_hw);
        cudaGetSymbolAddress((void**)&q,   g_q);
        cudaGetSymbolAddress((void**)&ao,  g_ao);
        cudaGetSymbolAddress((void**)&x1,  g_x1);
        cudaGetSymbolAddress((void**)&h2,  g_h2);
        cudaGetSymbolAddress((void**)&mid, g_mid);
    }

    const float qscale = 0.17677669529663687f;  // 32^-0.5

    // 1. LN1 + window partition
    ln_kernel<<<MROWS, 128>>>(x, g1, b1, hw, 1);

    // 2. q = (hw @ Wqkv[:, :384] + bqkv[:384]) * scale  -> (B_, NH, N, HD)
    sgemm_kernel<EPI_Q><<<dim3(3, 392), 256>>>(hw, Wqkv, 384, 384, 1152, 0,
                                               bqkv, q, nullptr, qscale);

    // 3. windowed attention
    attn_kernel<<<BWIN * NHEADS, 256>>>(q, kv, rel, btab, ao);

    // 4. proj + window_reverse + residual -> x1 (natural layout)
    sgemm_kernel<EPI_PROJ><<<dim3(3, 392), 256>>>(ao, Wproj, 384, 384, 384, 0,
                                                  bproj, x1, x, 0.0f);

    // 5. LN2
    ln_kernel<<<MROWS, 128>>>(x1, g2, b2, h2, 0);

    // 6. mid = gelu(h2 @ Wfc1 + bfc1)
    sgemm_kernel<EPI_GELU><<<dim3(12, 392), 256>>>(h2, Wfc1, 384, 384, 1536, 1536,
                                                   bfc1, mid, nullptr, 0.0f);

    // 7. out = x1 + mid @ Wfc2 + bfc2
    sgemm_kernel<EPI_FC2><<<dim3(3, 392), 256>>>(mid, Wfc2, 1536, 1536, 384, 384,
                                                 bfc2, out, x1, 0.0f);
}

// round 3
// speedup vs baseline: 1.6661x; 1.6661x over previous
#include <cuda_runtime.h>
#include <cuda_bf16.h>
#include <math.h>

// Problem constants
#define MROWS  50176
#define CDIM   384
#define HIDDEN 1536
#define NHEADS 12
#define HDIM   32
#define NWIN   49
#define BWIN   1024

typedef __nv_bfloat16 bf16;

// -------- scratch (device globals; no allocations allowed) --------
__device__ float g_q [(size_t)MROWS * CDIM];
__device__ float g_x1[(size_t)MROWS * CDIM];
__device__ bf16 g_hw_h[(size_t)MROWS * CDIM],  g_hw_l[(size_t)MROWS * CDIM];
__device__ bf16 g_ao_h[(size_t)MROWS * CDIM],  g_ao_l[(size_t)MROWS * CDIM];
__device__ bf16 g_h2_h[(size_t)MROWS * CDIM],  g_h2_l[(size_t)MROWS * CDIM];
__device__ bf16 g_mid_h[(size_t)MROWS * HIDDEN], g_mid_l[(size_t)MROWS * HIDDEN];
__device__ bf16 g_wq_h[384 * 384],  g_wq_l[384 * 384];
__device__ bf16 g_wp_h[384 * 384],  g_wp_l[384 * 384];
__device__ bf16 g_w1_h[384 * 1536], g_w1_l[384 * 1536];
__device__ bf16 g_w2_h[1536 * 384], g_w2_l[1536 * 384];

// ================= PTX helpers (portable sm_80+ path) =================
__device__ __forceinline__ unsigned smem_u32(const void* p) {
    unsigned a;
    asm("{ .reg .u64 t; cvta.to.shared.u64 t, %1; cvt.u32.u64 %0, t; }" : "=r"(a) : "l"(p));
    return a;
}
__device__ __forceinline__ void cp16(unsigned dst, const void* src) {
    asm volatile("cp.async.cg.shared.global [%0], [%1], 16;" :: "r"(dst), "l"(src) : "memory");
}
#define CP_COMMIT() asm volatile("cp.async.commit_group;" ::: "memory")
#define CP_WAIT(n)  asm volatile("cp.async.wait_group %0;" :: "n"(n) : "memory")

#define LDSM4(r, a)                                                                \
    asm volatile("ldmatrix.sync.aligned.m8n8.x4.shared.b16 {%0,%1,%2,%3}, [%4];"   \
        : "=r"((r)[0]), "=r"((r)[1]), "=r"((r)[2]), "=r"((r)[3]) : "r"(a))

#define MMA_BF16(d, a, b0, b1)                                                     \
    asm volatile("mma.sync.aligned.m16n8k16.row.col.f32.bf16.bf16.f32 "            \
        "{%0,%1,%2,%3}, {%4,%5,%6,%7}, {%8,%9}, {%0,%1,%2,%3};"                    \
        : "+f"((d)[0]), "+f"((d)[1]), "+f"((d)[2]), "+f"((d)[3])                    \
        : "r"((a)[0]), "r"((a)[1]), "r"((a)[2]), "r"((a)[3]), "r"(b0), "r"(b1))

__device__ __forceinline__ void split1(float v, bf16& h, bf16& l) {
    h = __float2bfloat16_rn(v);
    l = __float2bfloat16_rn(v - __bfloat162float(h));
}

// ============================================================
// Weight convert + transpose: W (Kd x Nd, row-major, lead ld, col off)
//   -> hi/lo (Nd x Kd bf16 row-major)
// ============================================================
__global__ void conv_w(const float* __restrict__ W, bf16* __restrict__ hi,
                       bf16* __restrict__ lo, int Kd, int Nd, int ld, int off)
{
    int idx = blockIdx.x * 256 + threadIdx.x;
    if (idx >= Kd * Nd) return;
    int k = idx / Nd, n = idx - k * Nd;
    float v = W[(size_t)k * ld + n + off];
    bf16 h, l; split1(v, h, l);
    hi[(size_t)n * Kd + k] = h;
    lo[(size_t)n * Kd + k] = l;
}

// ============================================================
// LayerNorm -> bf16 hi/lo (windowed=1: window-partition read order)
// ============================================================
__global__ void ln_kernel(const float* __restrict__ xin, const float* __restrict__ g,
                          const float* __restrict__ bb, bf16* __restrict__ oh,
                          bf16* __restrict__ ol, int windowed)
{
    int r = blockIdx.x;
    size_t srow;
    if (windowed) {
        int w = r / NWIN, n = r % NWIN;
        int bimg = w >> 6, wy = (w >> 3) & 7, wx = w & 7;
        int iy = n / 7, ix = n % 7;
        srow = (size_t)bimg * 3136 + (wy * 7 + iy) * 56 + (wx * 7 + ix);
    } else srow = (size_t)r;
    const float* xr = xin + srow * CDIM;
    int tid = threadIdx.x;
    float v0 = xr[tid], v1 = xr[tid + 128], v2 = xr[tid + 256];
    float s = v0 + v1 + v2, ss = v0 * v0 + v1 * v1 + v2 * v2;
    #pragma unroll
    for (int o = 16; o; o >>= 1) {
        s  += __shfl_xor_sync(0xffffffffu, s,  o);
        ss += __shfl_xor_sync(0xffffffffu, ss, o);
    }
    __shared__ float rs[4], rss[4], smean, sinv;
    int warp = tid >> 5, lane = tid & 31;
    if (lane == 0) { rs[warp] = s; rss[warp] = ss; }
    __syncthreads();
    if (tid == 0) {
        float S = rs[0] + rs[1] + rs[2] + rs[3];
        float SS = rss[0] + rss[1] + rss[2] + rss[3];
        float m = S * (1.0f / 384.0f);
        smean = m;
        sinv = rsqrtf(SS * (1.0f / 384.0f) - m * m + 1e-5f);
    }
    __syncthreads();
    size_t orow = (size_t)r * CDIM;
    #pragma unroll
    for (int c = 0; c < 3; ++c) {
        float vv = (c == 0 ? v0 : c == 1 ? v1 : v2);
        int col = tid + c * 128;
        float y = (vv - smean) * sinv * g[col] + bb[col];
        bf16 h, l; split1(y, h, l);
        oh[orow + col] = h; ol[orow + col] = l;
    }
}

// ============================================================
// split-bf16 tensor-core GEMM (mma.sync), 128x128 tile, KC=32,
// cp.async double buffer. A: MxK bf16 (hi/lo). B: NxK bf16 (hi/lo).
// ============================================================
enum { EPI_Q = 0, EPI_PROJ = 1, EPI_GELU = 2, EPI_FC2 = 3 };
#define TILE_B   10240          // 128 rows * 80B pitch
#define STAGE_B  40960
#define SMEM_DYN 81920

template <int EPI>
__global__ void __launch_bounds__(256)
mma_gemm(const bf16* __restrict__ Ah, const bf16* __restrict__ Al,
         const bf16* __restrict__ Bh, const bf16* __restrict__ Bl,
         int K, const float* __restrict__ bias,
         float* __restrict__ Cf, bf16* __restrict__ Ch, bf16* __restrict__ Cl,
         const float* __restrict__ resid, float scale)
{
    extern __shared__ char sm_raw[];
    unsigned sbase = smem_u32(sm_raw);

    int tid = threadIdx.x, wid = tid >> 5, lane = tid & 31;
    int bm = blockIdx.y * 128, bn = blockIdx.x * 128;
    int m0 = (wid & 3) * 32, n0 = (wid >> 2) * 64;

    const bf16* srcs[4] = { Ah, Al, Bh, Bl };

    // per-thread load slots: 8 x 16B cp.async per stage
    int rowA[8], chA[8];
    #pragma unroll
    for (int t = 0; t < 8; ++t) {
        int item = tid + t * 256;
        int rem = item & 511;
        rowA[t] = rem >> 2; chA[t] = rem & 3;
    }

    auto load_stage = [&](int stage, int k0) {
        unsigned db = sbase + stage * STAGE_B;
        #pragma unroll
        for (int t = 0; t < 8; ++t) {
            int tile = t >> 1;
            int grow = (tile < 2 ? bm : bn) + rowA[t];
            const bf16* src = srcs[tile] + (size_t)grow * K + k0 + chA[t] * 8;
            cp16(db + tile * TILE_B + rowA[t] * 80 + chA[t] * 16, src);
        }
        CP_COMMIT();
    };

    float acc[2][8][4];
    #pragma unroll
    for (int a = 0; a < 2; ++a)
        #pragma unroll
        for (int b = 0; b < 8; ++b)
            #pragma unroll
            for (int c = 0; c < 4; ++c) acc[a][b][c] = 0.0f;

    int niter = K >> 5;
    load_stage(0, 0);

    for (int it = 0; it < niter; ++it) {
        if (it + 1 < niter) { load_stage((it + 1) & 1, (it + 1) * 32); CP_WAIT(1); }
        else CP_WAIT(0);
        __syncthreads();

        unsigned base = sbase + (it & 1) * STAGE_B;
        #pragma unroll
        for (int ks = 0; ks < 2; ++ks) {
            unsigned ah[2][4], al[2][4];
            #pragma unroll
            for (int mt = 0; mt < 2; ++mt) {
                unsigned ra = base + (m0 + mt * 16 + (lane & 15)) * 80
                            + (ks * 2 + (lane >> 4)) * 16;
                LDSM4(ah[mt], ra);
                LDSM4(al[mt], ra + TILE_B);
            }
            #pragma unroll
            for (int nt = 0; nt < 4; ++nt) {
                unsigned rb = base + 2 * TILE_B + (n0 + nt * 16 + (lane & 15)) * 80
                            + (ks * 2 + (lane >> 4)) * 16;
                unsigned bh[4], bl[4];
                LDSM4(bh, rb);
                LDSM4(bl, rb + TILE_B);
                #pragma unroll
                for (int mt = 0; mt < 2; ++mt) {
                    MMA_BF16(acc[mt][nt * 2 + 0], ah[mt], bh[0], bh[2]);
                    MMA_BF16(acc[mt][nt * 2 + 0], ah[mt], bl[0], bl[2]);
                    MMA_BF16(acc[mt][nt * 2 + 0], al[mt], bh[0], bh[2]);
                    MMA_BF16(acc[mt][nt * 2 + 1], ah[mt], bh[1], bh[3]);
                    MMA_BF16(acc[mt][nt * 2 + 1], ah[mt], bl[1], bl[3]);
                    MMA_BF16(acc[mt][nt * 2 + 1], al[mt], bh[1], bh[3]);
                }
            }
        }
        __syncthreads();
    }

    // ---------------- epilogue ----------------
    int r_in = lane >> 2, c_in = (lane & 3) * 2;
    #pragma unroll
    for (int mt = 0; mt < 2; ++mt) {
        #pragma unroll
        for (int j = 0; j < 8; ++j) {
            int col = bn + n0 + j * 8 + c_in;
            #pragma unroll
            for (int hf = 0; hf < 2; ++hf) {
                int row = bm + m0 + mt * 16 + r_in + hf * 8;
                float v0 = acc[mt][j][hf * 2 + 0];
                float v1 = acc[mt][j][hf * 2 + 1];
                if (EPI == EPI_Q) {
                    int w = row / NWIN, n = row % NWIN;
                    int hd = col >> 5, d = col & 31;
                    float2 st = make_float2((v0 + bias[col]) * scale,
                                            (v1 + bias[col + 1]) * scale);
                    *(float2*)&Cf[((size_t)(w * NHEADS + hd) * NWIN + n) * HDIM + d] = st;
                } else if (EPI == EPI_PROJ) {
                    int w = row / NWIN, n = row % NWIN;
                    int bimg = w >> 6, wy = (w >> 3) & 7, wx = w & 7;
                    int iy = n / 7, ix = n % 7;
                    size_t o = ((size_t)bimg * 3136 + (wy * 7 + iy) * 56 + (wx * 7 + ix)) * CDIM + col;
                    float2 r2 = *(const float2*)&resid[o];
                    *(float2*)&Cf[o] = make_float2(v0 + bias[col] + r2.x,
                                                   v1 + bias[col + 1] + r2.y);
                } else if (EPI == EPI_GELU) {
                    float a0 = v0 + bias[col], a1 = v1 + bias[col + 1];
                    float g0 = 0.5f * a0 * (1.0f + erff(a0 * 0.70710678118654752f));
                    float g1 = 0.5f * a1 * (1.0f + erff(a1 * 0.70710678118654752f));
                    bf16 h0, l0, h1, l1;
                    split1(g0, h0, l0); split1(g1, h1, l1);
                    size_t o = (size_t)row * HIDDEN + col;
                    __nv_bfloat162 hp, lp;
                    hp.x = h0; hp.y = h1; lp.x = l0; lp.y = l1;
                    *(__nv_bfloat162*)&Ch[o] = hp;
                    *(__nv_bfloat162*)&Cl[o] = lp;
                } else {  // EPI_FC2
                    size_t o = (size_t)row * CDIM + col;
                    float2 r2 = *(const float2*)&resid[o];
                    *(float2*)&Cf[o] = make_float2(v0 + bias[col] + r2.x,
                                                   v1 + bias[col + 1] + r2.y);
                }
            }
        }
    }
}

// ============================================================
// Windowed attention (fp32 in, bf16 hi/lo out)
// ============================================================
__global__ void __launch_bounds__(256)
attn_kernel(const float* __restrict__ q, const float* __restrict__ kv,
            const int* __restrict__ rel, const float* __restrict__ btab,
            bf16* __restrict__ aoh, bf16* __restrict__ aol)
{
    __shared__ float sq[NWIN * HDIM];
    __shared__ float sk[NWIN * HDIM];
    __shared__ float sv[NWIN * HDIM];
    __shared__ float sS[NWIN * 52];

    int blk = blockIdx.x;
    int w = blk / NHEADS, h = blk - w * NHEADS;
    int bimg = w >> 6;
    int tid = threadIdx.x;

    const float* qp = q + (size_t)blk * (NWIN * HDIM);
    const float* kp = kv + (size_t)(bimg * NHEADS + h) * (NWIN * HDIM);
    const float* vp = kp + (size_t)16 * NHEADS * NWIN * HDIM;

    for (int t = tid; t < NWIN * HDIM; t += 256) {
        sq[t] = qp[t]; sk[t] = kp[t]; sv[t] = vp[t];
    }
    __syncthreads();

    for (int t = tid; t < NWIN * NWIN; t += 256) {
        int i = t / NWIN, j = t - i * NWIN;
        float s = 0.0f;
        #pragma unroll
        for (int d = 0; d < HDIM; ++d) s += sq[i * HDIM + d] * sk[j * HDIM + d];
        s += btab[rel[t] * NHEADS + h];
        sS[i * 52 + j] = s;
    }
    __syncthreads();

    int warp = tid >> 5, lane = tid & 31;
    for (int i = warp; i < NWIN; i += 8) {
        float v1 = sS[i * 52 + lane];
        float v2 = (lane + 32 < NWIN) ? sS[i * 52 + lane + 32] : -1e30f;
        float m = fmaxf(v1, v2);
        #pragma unroll
        for (int o = 16; o; o >>= 1) m = fmaxf(m, __shfl_xor_sync(0xffffffffu, m, o));
        float e1 = expf(v1 - m);
        float e2 = (lane + 32 < NWIN) ? expf(v2 - m) : 0.0f;
        float s = e1 + e2;
        #pragma unroll
        for (int o = 16; o; o >>= 1) s += __shfl_xor_sync(0xffffffffu, s, o);
        float inv = 1.0f / s;
        sS[i * 52 + lane] = e1 * inv;
        if (lane + 32 < NWIN) sS[i * 52 + lane + 32] = e2 * inv;
    }
    __syncthreads();

    for (int t = tid; t < NWIN * HDIM; t += 256) {
        int i = t >> 5, d = t & 31;
        float o = 0.0f;
        #pragma unroll
        for (int j = 0; j < NWIN; ++j) o += sS[i * 52 + j] * sv[j * HDIM + d];
        size_t oo = ((size_t)w * NWIN + i) * CDIM + h * HDIM + d;
        bf16 hh, ll; split1(o, hh, ll);
        aoh[oo] = hh; aol[oo] = ll;
    }
}

// ============================================================
// launch
// ============================================================
extern "C" void kernel_launch(void* const* d_in, const int* in_sizes, int n_in,
                              void* d_out, int out_size)
{
    (void)in_sizes; (void)n_in; (void)out_size;
    const float* x     = (const float*)d_in[0];
    const float* kv    = (const float*)d_in[1];
    const int*   rel   = (const int*)d_in[2];
    const float* g1    = (const float*)d_in[5];
    const float* b1    = (const float*)d_in[6];
    const float* Wqkv  = (const float*)d_in[7];
    const float* bqkv  = (const float*)d_in[8];
    const float* btab  = (const float*)d_in[9];
    const float* Wproj = (const float*)d_in[10];
    const float* bproj = (const float*)d_in[11];
    const float* g2    = (const float*)d_in[12];
    const float* b2    = (const float*)d_in[13];
    const float* Wfc1  = (const float*)d_in[14];
    const float* bfc1  = (const float*)d_in[15];
    const float* Wfc2  = (const float*)d_in[16];
    const float* bfc2  = (const float*)d_in[17];
    float* out = (float*)d_out;

    static float *q = nullptr, *x1 = nullptr;
    static bf16 *hwh, *hwl, *aoh, *aol, *h2h, *h2l, *midh, *midl;
    static bf16 *wqh, *wql, *wph, *wpl, *w1h, *w1l, *w2h, *w2l;
    if (!q) {
        cudaGetSymbolAddress((void**)&q,    g_q);
        cudaGetSymbolAddress((void**)&x1,   g_x1);
        cudaGetSymbolAddress((void**)&hwh,  g_hw_h);  cudaGetSymbolAddress((void**)&hwl, g_hw_l);
        cudaGetSymbolAddress((void**)&aoh,  g_ao_h);  cudaGetSymbolAddress((void**)&aol, g_ao_l);
        cudaGetSymbolAddress((void**)&h2h,  g_h2_h);  cudaGetSymbolAddress((void**)&h2l, g_h2_l);
        cudaGetSymbolAddress((void**)&midh, g_mid_h); cudaGetSymbolAddress((void**)&midl, g_mid_l);
        cudaGetSymbolAddress((void**)&wqh,  g_wq_h);  cudaGetSymbolAddress((void**)&wql, g_wq_l);
        cudaGetSymbolAddress((void**)&wph,  g_wp_h);  cudaGetSymbolAddress((void**)&wpl, g_wp_l);
        cudaGetSymbolAddress((void**)&w1h,  g_w1_h);  cudaGetSymbolAddress((void**)&w1l, g_w1_l);
        cudaGetSymbolAddress((void**)&w2h,  g_w2_h);  cudaGetSymbolAddress((void**)&w2l, g_w2_l);
        cudaFuncSetAttribute(mma_gemm<EPI_Q>,    cudaFuncAttributeMaxDynamicSharedMemorySize, SMEM_DYN);
        cudaFuncSetAttribute(mma_gemm<EPI_PROJ>, cudaFuncAttributeMaxDynamicSharedMemorySize, SMEM_DYN);
        cudaFuncSetAttribute(mma_gemm<EPI_GELU>, cudaFuncAttributeMaxDynamicSharedMemorySize, SMEM_DYN);
        cudaFuncSetAttribute(mma_gemm<EPI_FC2>,  cudaFuncAttributeMaxDynamicSharedMemorySize, SMEM_DYN);
    }

    const float qscale = 0.17677669529663687f;

    // weight conversions (tiny)
    conv_w<<<(384 * 384 + 255) / 256, 256>>>(Wqkv,  wqh, wql, 384, 384, 1152, 0);
    conv_w<<<(384 * 384 + 255) / 256, 256>>>(Wproj, wph, wpl, 384, 384, 384, 0);
    conv_w<<<(384 * 1536 + 255) / 256, 256>>>(Wfc1, w1h, w1l, 384, 1536, 1536, 0);
    conv_w<<<(1536 * 384 + 255) / 256, 256>>>(Wfc2, w2h, w2l, 1536, 384, 384, 0);

    // 1. LN1 + window partition -> bf16 hi/lo
    ln_kernel<<<MROWS, 128>>>(x, g1, b1, hwh, hwl, 1);

    // 2. q GEMM
    mma_gemm<EPI_Q><<<dim3(3, 392), 256, SMEM_DYN>>>(hwh, hwl, wqh, wql, 384,
        bqkv, q, nullptr, nullptr, nullptr, qscale);

    // 3. attention
    attn_kernel<<<BWIN * NHEADS, 256>>>(q, kv, rel, btab, aoh, aol);

    // 4. proj + window_reverse + residual
    mma_gemm<EPI_PROJ><<<dim3(3, 392), 256, SMEM_DYN>>>(aoh, aol, wph, wpl, 384,
        bproj, x1, nullptr, nullptr, x, 0.0f);

    // 5. LN2 -> bf16 hi/lo
    ln_kernel<<<MROWS, 128>>>(x1, g2, b2, h2h, h2l, 0);

    // 6. fc1 + GELU -> bf16 hi/lo
    mma_gemm<EPI_GELU><<<dim3(12, 392), 256, SMEM_DYN>>>(h2h, h2l, w1h, w1l, 384,
        bfc1, nullptr, midh, midl, nullptr, 0.0f);

    // 7. fc2 + residual -> out
    mma_gemm<EPI_FC2><<<dim3(3, 392), 256, SMEM_DYN>>>(midh, midl, w2h, w2l, 1536,
        bfc2, out, nullptr, nullptr, x1, 0.0f);
}

// round 4
// speedup vs baseline: 4.1618x; 2.4979x over previous
#include <cuda_runtime.h>
#include <cuda_fp16.h>
#include <math.h>

// Problem constants
#define MROWS  50176
#define CDIM   384
#define HIDDEN 1536
#define NHEADS 12
#define HDIM   32
#define NWIN   49
#define BWIN   1024

typedef __half fp16;

// -------- scratch (device globals; no allocations allowed) --------
__device__ float g_q [(size_t)MROWS * CDIM];
__device__ float g_x1[(size_t)MROWS * CDIM];
__device__ fp16 g_hw [(size_t)MROWS * CDIM];
__device__ fp16 g_ao [(size_t)MROWS * CDIM];
__device__ fp16 g_h2 [(size_t)MROWS * CDIM];
__device__ fp16 g_mid[(size_t)MROWS * HIDDEN];
__device__ fp16 g_wq [384 * 384];
__device__ fp16 g_wp [384 * 384];
__device__ fp16 g_w1 [384 * 1536];
__device__ fp16 g_w2 [1536 * 384];

// ================= PTX helpers =================
__device__ __forceinline__ unsigned smem_u32(const void* p) {
    unsigned a;
    asm("{ .reg .u64 t; cvta.to.shared.u64 t, %1; cvt.u32.u64 %0, t; }" : "=r"(a) : "l"(p));
    return a;
}
__device__ __forceinline__ void cp16(unsigned dst, const void* src) {
    asm volatile("cp.async.cg.shared.global [%0], [%1], 16;" :: "r"(dst), "l"(src) : "memory");
}
#define CP_COMMIT() asm volatile("cp.async.commit_group;" ::: "memory")
#define CP_WAIT(n)  asm volatile("cp.async.wait_group %0;" :: "n"(n) : "memory")

#define LDSM4(r, a)                                                                \
    asm volatile("ldmatrix.sync.aligned.m8n8.x4.shared.b16 {%0,%1,%2,%3}, [%4];"   \
        : "=r"((r)[0]), "=r"((r)[1]), "=r"((r)[2]), "=r"((r)[3]) : "r"(a))

#define MMA_F16(d, a, b0, b1)                                                      \
    asm volatile("mma.sync.aligned.m16n8k16.row.col.f32.f16.f16.f32 "              \
        "{%0,%1,%2,%3}, {%4,%5,%6,%7}, {%8,%9}, {%0,%1,%2,%3};"                    \
        : "+f"((d)[0]), "+f"((d)[1]), "+f"((d)[2]), "+f"((d)[3])                    \
        : "r"((a)[0]), "r"((a)[1]), "r"((a)[2]), "r"((a)[3]), "r"(b0), "r"(b1))

// ============================================================
// Weight convert + transpose: W (Kd x Nd rows, lead ld, col off)
//   -> fp16 (Nd x Kd row-major)
// ============================================================
__global__ void conv_w(const float* __restrict__ W, fp16* __restrict__ o,
                       int Kd, int Nd, int ld, int off)
{
    int idx = blockIdx.x * 256 + threadIdx.x;
    if (idx >= Kd * Nd) return;
    int k = idx / Nd, n = idx - k * Nd;
    o[(size_t)n * Kd + k] = __float2half_rn(W[(size_t)k * ld + n + off]);
}

// ============================================================
// LayerNorm -> fp16 (windowed=1: window-partition read order)
// ============================================================
__global__ void ln_kernel(const float* __restrict__ xin, const float* __restrict__ g,
                          const float* __restrict__ bb, fp16* __restrict__ oh,
                          int windowed)
{
    int r = blockIdx.x;
    size_t srow;
    if (windowed) {
        int w = r / NWIN, n = r % NWIN;
        int bimg = w >> 6, wy = (w >> 3) & 7, wx = w & 7;
        int iy = n / 7, ix = n % 7;
        srow = (size_t)bimg * 3136 + (wy * 7 + iy) * 56 + (wx * 7 + ix);
    } else srow = (size_t)r;
    const float* xr = xin + srow * CDIM;
    int tid = threadIdx.x;
    float v0 = xr[tid], v1 = xr[tid + 128], v2 = xr[tid + 256];
    float s = v0 + v1 + v2, ss = v0 * v0 + v1 * v1 + v2 * v2;
    #pragma unroll
    for (int o = 16; o; o >>= 1) {
        s  += __shfl_xor_sync(0xffffffffu, s,  o);
        ss += __shfl_xor_sync(0xffffffffu, ss, o);
    }
    __shared__ float rs[4], rss[4], smean, sinv;
    int warp = tid >> 5, lane = tid & 31;
    if (lane == 0) { rs[warp] = s; rss[warp] = ss; }
    __syncthreads();
    if (tid == 0) {
        float S = rs[0] + rs[1] + rs[2] + rs[3];
        float SS = rss[0] + rss[1] + rss[2] + rss[3];
        float m = S * (1.0f / 384.0f);
        smean = m;
        sinv = rsqrtf(SS * (1.0f / 384.0f) - m * m + 1e-5f);
    }
    __syncthreads();
    size_t orow = (size_t)r * CDIM;
    #pragma unroll
    for (int c = 0; c < 3; ++c) {
        float vv = (c == 0 ? v0 : c == 1 ? v1 : v2);
        int col = tid + c * 128;
        oh[orow + col] = __float2half_rn((vv - smean) * sinv * g[col] + bb[col]);
    }
}

// ============================================================
// fp16 tensor-core GEMM (mma.sync), 128x128 tile, KC=32,
// cp.async double buffer. A: MxK fp16. B: NxK fp16.
// ============================================================
enum { EPI_Q = 0, EPI_PROJ = 1, EPI_GELU = 2, EPI_FC2 = 3 };
#define TILE_B   10240          // 128 rows * 80B pitch
#define STAGE_B  20480
#define SMEM_DYN 40960

template <int EPI>
__global__ void __launch_bounds__(256, 2)
mma_gemm(const fp16* __restrict__ Am, const fp16* __restrict__ Bm,
         int K, const float* __restrict__ bias,
         float* __restrict__ Cf, fp16* __restrict__ Ch,
         const float* __restrict__ resid, float scale)
{
    extern __shared__ char sm_raw[];
    unsigned sbase = smem_u32(sm_raw);

    int tid = threadIdx.x, wid = tid >> 5, lane = tid & 31;
    int bm = blockIdx.y * 128, bn = blockIdx.x * 128;
    int m0 = (wid & 3) * 32, n0 = (wid >> 2) * 64;

    // per-thread load slots: 4 x 16B cp.async per stage (2 tiles x 512 items)
    int rowL[4], chL[4], tileL[4];
    #pragma unroll
    for (int t = 0; t < 4; ++t) {
        int item = tid + t * 256;
        tileL[t] = item >> 9;
        int rem = item & 511;
        rowL[t] = rem >> 2; chL[t] = rem & 3;
    }

    auto load_stage = [&](int stage, int k0) {
        unsigned db = sbase + stage * STAGE_B;
        #pragma unroll
        for (int t = 0; t < 4; ++t) {
            const fp16* src = (tileL[t] ? Bm : Am)
                + (size_t)((tileL[t] ? bn : bm) + rowL[t]) * K + k0 + chL[t] * 8;
            cp16(db + tileL[t] * TILE_B + rowL[t] * 80 + chL[t] * 16, src);
        }
        CP_COMMIT();
    };

    float acc[2][8][4];
    #pragma unroll
    for (int a = 0; a < 2; ++a)
        #pragma unroll
        for (int b = 0; b < 8; ++b)
            #pragma unroll
            for (int c = 0; c < 4; ++c) acc[a][b][c] = 0.0f;

    int niter = K >> 5;
    load_stage(0, 0);

    for (int it = 0; it < niter; ++it) {
        if (it + 1 < niter) { load_stage((it + 1) & 1, (it + 1) * 32); CP_WAIT(1); }
        else CP_WAIT(0);
        __syncthreads();

        unsigned base = sbase + (it & 1) * STAGE_B;
        #pragma unroll
        for (int ks = 0; ks < 2; ++ks) {
            unsigned ah[2][4];
            #pragma unroll
            for (int mt = 0; mt < 2; ++mt) {
                unsigned ra = base + (m0 + mt * 16 + (lane & 15)) * 80
                            + (ks * 2 + (lane >> 4)) * 16;
                LDSM4(ah[mt], ra);
            }
            #pragma unroll
            for (int nt = 0; nt < 4; ++nt) {
                unsigned rb = base + TILE_B + (n0 + nt * 16 + (lane & 15)) * 80
                            + (ks * 2 + (lane >> 4)) * 16;
                unsigned bh[4];
                LDSM4(bh, rb);
                #pragma unroll
                for (int mt = 0; mt < 2; ++mt) {
                    MMA_F16(acc[mt][nt * 2 + 0], ah[mt], bh[0], bh[2]);
                    MMA_F16(acc[mt][nt * 2 + 1], ah[mt], bh[1], bh[3]);
                }
            }
        }
        __syncthreads();
    }

    // ---------------- epilogue ----------------
    int r_in = lane >> 2, c_in = (lane & 3) * 2;
    #pragma unroll
    for (int mt = 0; mt < 2; ++mt) {
        #pragma unroll
        for (int j = 0; j < 8; ++j) {
            int col = bn + n0 + j * 8 + c_in;
            #pragma unroll
            for (int hf = 0; hf < 2; ++hf) {
                int row = bm + m0 + mt * 16 + r_in + hf * 8;
                float v0 = acc[mt][j][hf * 2 + 0];
                float v1 = acc[mt][j][hf * 2 + 1];
                if (EPI == EPI_Q) {
                    int w = row / NWIN, n = row % NWIN;
                    int hd = col >> 5, d = col & 31;
                    float2 st = make_float2((v0 + bias[col]) * scale,
                                            (v1 + bias[col + 1]) * scale);
                    *(float2*)&Cf[((size_t)(w * NHEADS + hd) * NWIN + n) * HDIM + d] = st;
                } else if (EPI == EPI_PROJ) {
                    int w = row / NWIN, n = row % NWIN;
                    int bimg = w >> 6, wy = (w >> 3) & 7, wx = w & 7;
                    int iy = n / 7, ix = n % 7;
                    size_t o = ((size_t)bimg * 3136 + (wy * 7 + iy) * 56 + (wx * 7 + ix)) * CDIM + col;
                    float2 r2 = *(const float2*)&resid[o];
                    *(float2*)&Cf[o] = make_float2(v0 + bias[col] + r2.x,
                                                   v1 + bias[col + 1] + r2.y);
                } else if (EPI == EPI_GELU) {
                    float a0 = v0 + bias[col], a1 = v1 + bias[col + 1];
                    float g0 = 0.5f * a0 * (1.0f + erff(a0 * 0.70710678118654752f));
                    float g1 = 0.5f * a1 * (1.0f + erff(a1 * 0.70710678118654752f));
                    __half2 hp;
                    hp.x = __float2half_rn(g0); hp.y = __float2half_rn(g1);
                    *(__half2*)&Ch[(size_t)row * HIDDEN + col] = hp;
                } else {  // EPI_FC2
                    size_t o = (size_t)row * CDIM + col;
                    float2 r2 = *(const float2*)&resid[o];
                    *(float2*)&Cf[o] = make_float2(v0 + bias[col] + r2.x,
                                                   v1 + bias[col + 1] + r2.y);
                }
            }
        }
    }
}

// ============================================================
// Windowed attention: conflict-free (K stored transposed)
// ============================================================
__global__ void __launch_bounds__(256)
attn_kernel(const float* __restrict__ q, const float* __restrict__ kv,
            const int* __restrict__ rel, const float* __restrict__ btab,
            fp16* __restrict__ ao)
{
    __shared__ float sq[NWIN * HDIM];
    __shared__ float skt[HDIM * 52];      // transposed: [d][j], pitch 52
    __shared__ float sv[NWIN * HDIM];
    __shared__ float sS[NWIN * 52];

    int blk = blockIdx.x;
    int w = blk / NHEADS, h = blk - w * NHEADS;
    int bimg = w >> 6;
    int tid = threadIdx.x;

    const float* qp = q + (size_t)blk * (NWIN * HDIM);
    const float* kp = kv + (size_t)(bimg * NHEADS + h) * (NWIN * HDIM);
    const float* vp = kp + (size_t)16 * NHEADS * NWIN * HDIM;

    for (int t = tid; t < NWIN * HDIM; t += 256) {
        int j = t >> 5, d = t & 31;
        sq[t] = qp[t];
        skt[d * 52 + j] = kp[t];
        sv[t] = vp[t];
    }
    __syncthreads();

    for (int t = tid; t < NWIN * NWIN; t += 256) {
        int i = t / NWIN, j = t - i * NWIN;
        float s = 0.0f;
        #pragma unroll
        for (int d = 0; d < HDIM; ++d) s += sq[i * HDIM + d] * skt[d * 52 + j];
        s += btab[rel[t] * NHEADS + h];
        sS[i * 52 + j] = s;
    }
    __syncthreads();

    int warp = tid >> 5, lane = tid & 31;
    for (int i = warp; i < NWIN; i += 8) {
        float v1 = sS[i * 52 + lane];
        float v2 = (lane + 32 < NWIN) ? sS[i * 52 + lane + 32] : -1e30f;
        float m = fmaxf(v1, v2);
        #pragma unroll
        for (int o = 16; o; o >>= 1) m = fmaxf(m, __shfl_xor_sync(0xffffffffu, m, o));
        float e1 = __expf(v1 - m);
        float e2 = (lane + 32 < NWIN) ? __expf(v2 - m) : 0.0f;
        float s = e1 + e2;
        #pragma unroll
        for (int o = 16; o; o >>= 1) s += __shfl_xor_sync(0xffffffffu, s, o);
        float inv = 1.0f / s;
        sS[i * 52 + lane] = e1 * inv;
        if (lane + 32 < NWIN) sS[i * 52 + lane + 32] = e2 * inv;
    }
    __syncthreads();

    for (int t = tid; t < NWIN * HDIM; t += 256) {
        int i = t >> 5, d = t & 31;
        float o = 0.0f;
        #pragma unroll
        for (int j = 0; j < NWIN; ++j) o += sS[i * 52 + j] * sv[j * HDIM + d];
        ao[((size_t)w * NWIN + i) * CDIM + h * HDIM + d] = __float2half_rn(o);
    }
}

// ============================================================
// launch
// ============================================================
extern "C" void kernel_launch(void* const* d_in, const int* in_sizes, int n_in,
                              void* d_out, int out_size)
{
    (void)in_sizes; (void)n_in; (void)out_size;
    const float* x     = (const float*)d_in[0];
    const float* kv    = (const float*)d_in[1];
    const int*   rel   = (const int*)d_in[2];
    const float* g1    = (const float*)d_in[5];
    const float* b1    = (const float*)d_in[6];
    const float* Wqkv  = (const float*)d_in[7];
    const float* bqkv  = (const float*)d_in[8];
    const float* btab  = (const float*)d_in[9];
    const float* Wproj = (const float*)d_in[10];
    const float* bproj = (const float*)d_in[11];
    const float* g2    = (const float*)d_in[12];
    const float* b2    = (const float*)d_in[13];
    const float* Wfc1  = (const float*)d_in[14];
    const float* bfc1  = (const float*)d_in[15];
    const float* Wfc2  = (const float*)d_in[16];
    const float* bfc2  = (const float*)d_in[17];
    float* out = (float*)d_out;

    static float *q = nullptr, *x1 = nullptr;
    static fp16 *hw, *ao, *h2, *mid, *wq, *wp, *w1, *w2;
    if (!q) {
        cudaGetSymbolAddress((void**)&q,   g_q);
        cudaGetSymbolAddress((void**)&x1,  g_x1);
        cudaGetSymbolAddress((void**)&hw,  g_hw);
        cudaGetSymbolAddress((void**)&ao,  g_ao);
        cudaGetSymbolAddress((void**)&h2,  g_h2);
        cudaGetSymbolAddress((void**)&mid, g_mid);
        cudaGetSymbolAddress((void**)&wq,  g_wq);
        cudaGetSymbolAddress((void**)&wp,  g_wp);
        cudaGetSymbolAddress((void**)&w1,  g_w1);
        cudaGetSymbolAddress((void**)&w2,  g_w2);
        cudaFuncSetAttribute(mma_gemm<EPI_Q>,    cudaFuncAttributeMaxDynamicSharedMemorySize, SMEM_DYN);
        cudaFuncSetAttribute(mma_gemm<EPI_PROJ>, cudaFuncAttributeMaxDynamicSharedMemorySize, SMEM_DYN);
        cudaFuncSetAttribute(mma_gemm<EPI_GELU>, cudaFuncAttributeMaxDynamicSharedMemorySize, SMEM_DYN);
        cudaFuncSetAttribute(mma_gemm<EPI_FC2>,  cudaFuncAttributeMaxDynamicSharedMemorySize, SMEM_DYN);
    }

    const float qscale = 0.17677669529663687f;

    // weight conversions (tiny)
    conv_w<<<(384 * 384 + 255) / 256, 256>>>(Wqkv,  wq, 384, 384, 1152, 0);
    conv_w<<<(384 * 384 + 255) / 256, 256>>>(Wproj, wp, 384, 384, 384, 0);
    conv_w<<<(384 * 1536 + 255) / 256, 256>>>(Wfc1, w1, 384, 1536, 1536, 0);
    conv_w<<<(1536 * 384 + 255) / 256, 256>>>(Wfc2, w2, 1536, 384, 384, 0);

    // 1. LN1 + window partition -> fp16
    ln_kernel<<<MROWS, 128>>>(x, g1, b1, hw, 1);

    // 2. q GEMM
    mma_gemm<EPI_Q><<<dim3(3, 392), 256, SMEM_DYN>>>(hw, wq, 384,
        bqkv, q, nullptr, nullptr, qscale);

    // 3. attention
    attn_kernel<<<BWIN * NHEADS, 256>>>(q, kv, rel, btab, ao);

    // 4. proj + window_reverse + residual
    mma_gemm<EPI_PROJ><<<dim3(3, 392), 256, SMEM_DYN>>>(ao, wp, 384,
        bproj, x1, nullptr, x, 0.0f);

    // 5. LN2 -> fp16
    ln_kernel<<<MROWS, 128>>>(x1, g2, b2, h2, 0);

    // 6. fc1 + GELU -> fp16
    mma_gemm<EPI_GELU><<<dim3(12, 392), 256, SMEM_DYN>>>(h2, w1, 384,
        bfc1, nullptr, mid, nullptr, 0.0f);

    // 7. fc2 + residual -> out
    mma_gemm<EPI_FC2><<<dim3(3, 392), 256, SMEM_DYN>>>(mid, w2, 1536,
        bfc2, out, nullptr, x1, 0.0f);
}

// round 5
// speedup vs baseline: 4.9649x; 1.1930x over previous
#include <cuda_runtime.h>
#include <cuda_fp16.h>
#include <math.h>

// Problem constants
#define MROWS  50176
#define CDIM   384
#define HIDDEN 1536
#define NHEADS 12
#define HDIM   32
#define NWIN   49
#define BWIN   1024

typedef __half fp16;

// -------- scratch (device globals; no allocations allowed) --------
__device__ float g_x1[(size_t)MROWS * CDIM];
__device__ fp16 g_hw [(size_t)MROWS * CDIM];
__device__ fp16 g_qh [(size_t)MROWS * CDIM];
__device__ fp16 g_ao [(size_t)MROWS * CDIM];
__device__ fp16 g_h2 [(size_t)MROWS * CDIM];
__device__ fp16 g_mid[(size_t)MROWS * HIDDEN];
__device__ fp16 g_wq [384 * 384];
__device__ fp16 g_wp [384 * 384];
__device__ fp16 g_w1 [384 * 1536];
__device__ fp16 g_w2 [1536 * 384];
__device__ float g_bmat[NHEADS * NWIN * NWIN];

// ================= PTX helpers =================
__device__ __forceinline__ unsigned smem_u32(const void* p) {
    unsigned a;
    asm("{ .reg .u64 t; cvta.to.shared.u64 t, %1; cvt.u32.u64 %0, t; }" : "=r"(a) : "l"(p));
    return a;
}
__device__ __forceinline__ void cp16(unsigned dst, const void* src) {
    asm volatile("cp.async.cg.shared.global [%0], [%1], 16;" :: "r"(dst), "l"(src) : "memory");
}
#define CP_COMMIT() asm volatile("cp.async.commit_group;" ::: "memory")
#define CP_WAIT(n)  asm volatile("cp.async.wait_group %0;" :: "n"(n) : "memory")

#define LDSM4(r, a)                                                                \
    asm volatile("ldmatrix.sync.aligned.m8n8.x4.shared.b16 {%0,%1,%2,%3}, [%4];"   \
        : "=r"((r)[0]), "=r"((r)[1]), "=r"((r)[2]), "=r"((r)[3]) : "r"(a))

#define MMA_F16(d, a, b0, b1)                                                      \
    asm volatile("mma.sync.aligned.m16n8k16.row.col.f32.f16.f16.f32 "              \
        "{%0,%1,%2,%3}, {%4,%5,%6,%7}, {%8,%9}, {%0,%1,%2,%3};"                    \
        : "+f"((d)[0]), "+f"((d)[1]), "+f"((d)[2]), "+f"((d)[3])                    \
        : "r"((a)[0]), "r"((a)[1]), "r"((a)[2]), "r"((a)[3]), "r"(b0), "r"(b1))

// ============================================================
// Fused weight conversions (4 matrices, one launch)
// W (Kd x Nd, lead ld) -> fp16 (Nd x Kd row-major)
// ============================================================
__global__ void conv_all(const float* __restrict__ Wq, const float* __restrict__ Wp,
                         const float* __restrict__ W1, const float* __restrict__ W2,
                         fp16* __restrict__ oq, fp16* __restrict__ op,
                         fp16* __restrict__ o1, fp16* __restrict__ o2)
{
    int b = blockIdx.x;
    const float* W; fp16* o; int Kd, Nd, ld, base;
    if (b < 576)        { W = Wq; o = oq; Kd = 384;  Nd = 384;  ld = 1152; base = 0; }
    else if (b < 1152)  { W = Wp; o = op; Kd = 384;  Nd = 384;  ld = 384;  base = 576; }
    else if (b < 3456)  { W = W1; o = o1; Kd = 384;  Nd = 1536; ld = 1536; base = 1152; }
    else                { W = W2; o = o2; Kd = 1536; Nd = 384;  ld = 384;  base = 3456; }
    int idx = (b - base) * 256 + threadIdx.x;
    if (idx >= Kd * Nd) return;
    int k = idx / Nd, n = idx - k * Nd;
    o[(size_t)n * Kd + k] = __float2half_rn(W[(size_t)k * ld + n]);
}

// ============================================================
// bias matrix precompute: bmat[h][i*49+j] = btab[rel[ij]*12+h]
// ============================================================
__global__ void bias_mat(const int* __restrict__ rel, const float* __restrict__ btab,
                         float* __restrict__ bm)
{
    int t = blockIdx.x * 256 + threadIdx.x;
    if (t >= NHEADS * NWIN * NWIN) return;
    int h = t / (NWIN * NWIN), ij = t % (NWIN * NWIN);
    bm[t] = btab[rel[ij] * NHEADS + h];
}

// ============================================================
// LayerNorm -> fp16
// ============================================================
__global__ void ln_kernel(const float* __restrict__ xin, const float* __restrict__ g,
                          const float* __restrict__ bb, fp16* __restrict__ oh,
                          int windowed)
{
    int r = blockIdx.x;
    size_t srow;
    if (windowed) {
        int w = r / NWIN, n = r % NWIN;
        int bimg = w >> 6, wy = (w >> 3) & 7, wx = w & 7;
        int iy = n / 7, ix = n % 7;
        srow = (size_t)bimg * 3136 + (wy * 7 + iy) * 56 + (wx * 7 + ix);
    } else srow = (size_t)r;
    const float* xr = xin + srow * CDIM;
    int tid = threadIdx.x;
    float v0 = xr[tid], v1 = xr[tid + 128], v2 = xr[tid + 256];
    float s = v0 + v1 + v2, ss = v0 * v0 + v1 * v1 + v2 * v2;
    #pragma unroll
    for (int o = 16; o; o >>= 1) {
        s  += __shfl_xor_sync(0xffffffffu, s,  o);
        ss += __shfl_xor_sync(0xffffffffu, ss, o);
    }
    __shared__ float rs[4], rss[4], smean, sinv;
    int warp = tid >> 5, lane = tid & 31;
    if (lane == 0) { rs[warp] = s; rss[warp] = ss; }
    __syncthreads();
    if (tid == 0) {
        float S = rs[0] + rs[1] + rs[2] + rs[3];
        float SS = rss[0] + rss[1] + rss[2] + rss[3];
        float m = S * (1.0f / 384.0f);
        smean = m;
        sinv = rsqrtf(SS * (1.0f / 384.0f) - m * m + 1e-5f);
    }
    __syncthreads();
    size_t orow = (size_t)r * CDIM;
    #pragma unroll
    for (int c = 0; c < 3; ++c) {
        float vv = (c == 0 ? v0 : c == 1 ? v1 : v2);
        int col = tid + c * 128;
        oh[orow + col] = __float2half_rn((vv - smean) * sinv * g[col] + bb[col]);
    }
}

// ============================================================
// fp16 tensor-core GEMM (mma.sync), 128x128 tile, KC=32
// ============================================================
enum { EPI_Q = 0, EPI_PROJ = 1, EPI_GELU = 2, EPI_FC2 = 3 };
#define TILE_B   10240
#define STAGE_B  20480
#define SMEM_DYN 40960

template <int EPI>
__global__ void __launch_bounds__(256, 2)
mma_gemm(const fp16* __restrict__ Am, const fp16* __restrict__ Bm,
         int K, const float* __restrict__ bias,
         float* __restrict__ Cf, fp16* __restrict__ Ch,
         const float* __restrict__ resid, float scale)
{
    extern __shared__ char sm_raw[];
    unsigned sbase = smem_u32(sm_raw);

    int tid = threadIdx.x, wid = tid >> 5, lane = tid & 31;
    int bm = blockIdx.y * 128, bn = blockIdx.x * 128;
    int m0 = (wid & 3) * 32, n0 = (wid >> 2) * 64;

    int rowL[4], chL[4], tileL[4];
    #pragma unroll
    for (int t = 0; t < 4; ++t) {
        int item = tid + t * 256;
        tileL[t] = item >> 9;
        int rem = item & 511;
        rowL[t] = rem >> 2; chL[t] = rem & 3;
    }

    auto load_stage = [&](int stage, int k0) {
        unsigned db = sbase + stage * STAGE_B;
        #pragma unroll
        for (int t = 0; t < 4; ++t) {
            const fp16* src = (tileL[t] ? Bm : Am)
                + (size_t)((tileL[t] ? bn : bm) + rowL[t]) * K + k0 + chL[t] * 8;
            cp16(db + tileL[t] * TILE_B + rowL[t] * 80 + chL[t] * 16, src);
        }
        CP_COMMIT();
    };

    float acc[2][8][4];
    #pragma unroll
    for (int a = 0; a < 2; ++a)
        #pragma unroll
        for (int b = 0; b < 8; ++b)
            #pragma unroll
            for (int c = 0; c < 4; ++c) acc[a][b][c] = 0.0f;

    int niter = K >> 5;
    load_stage(0, 0);

    for (int it = 0; it < niter; ++it) {
        if (it + 1 < niter) { load_stage((it + 1) & 1, (it + 1) * 32); CP_WAIT(1); }
        else CP_WAIT(0);
        __syncthreads();

        unsigned base = sbase + (it & 1) * STAGE_B;
        #pragma unroll
        for (int ks = 0; ks < 2; ++ks) {
            unsigned ah[2][4];
            #pragma unroll
            for (int mt = 0; mt < 2; ++mt) {
                unsigned ra = base + (m0 + mt * 16 + (lane & 15)) * 80
                            + (ks * 2 + (lane >> 4)) * 16;
                LDSM4(ah[mt], ra);
            }
            #pragma unroll
            for (int nt = 0; nt < 4; ++nt) {
                unsigned rb = base + TILE_B + (n0 + nt * 16 + (lane & 15)) * 80
                            + (ks * 2 + (lane >> 4)) * 16;
                unsigned bh[4];
                LDSM4(bh, rb);
                #pragma unroll
                for (int mt = 0; mt < 2; ++mt) {
                    MMA_F16(acc[mt][nt * 2 + 0], ah[mt], bh[0], bh[2]);
                    MMA_F16(acc[mt][nt * 2 + 1], ah[mt], bh[1], bh[3]);
                }
            }
        }
        __syncthreads();
    }

    int r_in = lane >> 2, c_in = (lane & 3) * 2;
    #pragma unroll
    for (int mt = 0; mt < 2; ++mt) {
        #pragma unroll
        for (int j = 0; j < 8; ++j) {
            int col = bn + n0 + j * 8 + c_in;
            #pragma unroll
            for (int hf = 0; hf < 2; ++hf) {
                int row = bm + m0 + mt * 16 + r_in + hf * 8;
                float v0 = acc[mt][j][hf * 2 + 0];
                float v1 = acc[mt][j][hf * 2 + 1];
                if (EPI == EPI_Q) {
                    int w = row / NWIN, n = row % NWIN;
                    int hd = col >> 5, d = col & 31;
                    __half2 hp;
                    hp.x = __float2half_rn((v0 + bias[col]) * scale);
                    hp.y = __float2half_rn((v1 + bias[col + 1]) * scale);
                    *(__half2*)&Ch[((size_t)(w * NHEADS + hd) * NWIN + n) * HDIM + d] = hp;
                } else if (EPI == EPI_PROJ) {
                    int w = row / NWIN, n = row % NWIN;
                    int bimg = w >> 6, wy = (w >> 3) & 7, wx = w & 7;
                    int iy = n / 7, ix = n % 7;
                    size_t o = ((size_t)bimg * 3136 + (wy * 7 + iy) * 56 + (wx * 7 + ix)) * CDIM + col;
                    float2 r2 = *(const float2*)&resid[o];
                    *(float2*)&Cf[o] = make_float2(v0 + bias[col] + r2.x,
                                                   v1 + bias[col + 1] + r2.y);
                } else if (EPI == EPI_GELU) {
                    float a0 = v0 + bias[col], a1 = v1 + bias[col + 1];
                    float g0 = 0.5f * a0 * (1.0f + erff(a0 * 0.70710678118654752f));
                    float g1 = 0.5f * a1 * (1.0f + erff(a1 * 0.70710678118654752f));
                    __half2 hp;
                    hp.x = __float2half_rn(g0); hp.y = __float2half_rn(g1);
                    *(__half2*)&Ch[(size_t)row * HIDDEN + col] = hp;
                } else {
                    size_t o = (size_t)row * CDIM + col;
                    float2 r2 = *(const float2*)&resid[o];
                    *(float2*)&Cf[o] = make_float2(v0 + bias[col] + r2.x,
                                                   v1 + bias[col + 1] + r2.y);
                }
            }
        }
    }
}

// ============================================================
// Tensor-core windowed attention. 1 block = 1 (window, head),
// 128 threads / 4 warps. S = q@k^T (padded 64x64), softmax+bias,
// O = P@V. Pads zeroed so padding contributes nothing.
// ============================================================
#define QK_PITCH 40   // halves (80 B): 5 units mod 8 -> ldmatrix conflict-free
#define PV_PITCH 72   // halves (144 B): 9 units mod 8 -> conflict-free
#define S_PITCH  66   // floats

__global__ void __launch_bounds__(128)
attn_tc(const fp16* __restrict__ q, const float* __restrict__ kv,
        const float* __restrict__ bmat, fp16* __restrict__ ao)
{
    __shared__ fp16 sq [64 * QK_PITCH];
    __shared__ fp16 sk [64 * QK_PITCH];
    __shared__ fp16 svt[32 * PV_PITCH];
    __shared__ float sS[64 * S_PITCH];
    __shared__ fp16 sP [64 * PV_PITCH];

    int blk = blockIdx.x;
    int w = blk / NHEADS, h = blk - w * NHEADS;
    int bimg = w >> 6;
    int tid = threadIdx.x, wid = tid >> 5, lane = tid & 31;

    const fp16*  qp = q + (size_t)blk * (NWIN * HDIM);
    const float* kp = kv + (size_t)(bimg * NHEADS + h) * (NWIN * HDIM);
    const float* vp = kp + (size_t)16 * NHEADS * NWIN * HDIM;

    // q: 1568 halves = 196 uint4
    for (int t = tid; t < 196; t += 128) {
        uint4 v = ((const uint4*)qp)[t];
        int row = t >> 2, col = (t & 3) * 8;
        *(uint4*)&sq[row * QK_PITCH + col] = v;
    }
    // q pad rows 49..63
    for (int t = tid; t < 60; t += 128) {
        int row = 49 + (t >> 2), col = (t & 3) * 8;
        *(uint4*)&sq[row * QK_PITCH + col] = make_uint4(0, 0, 0, 0);
    }
    // k fp32 -> fp16 (+pad), v -> transposed (+col pad)
    for (int t = tid; t < NWIN * HDIM; t += 128) {
        int row = t >> 5, col = t & 31;
        sk[row * QK_PITCH + col] = __float2half_rn(kp[t]);
        svt[col * PV_PITCH + row] = __float2half_rn(vp[t]);
    }
    for (int t = tid; t < 480; t += 128) {
        int row = 49 + (t >> 5), col = t & 31;
        sk[row * QK_PITCH + col] = __float2half_rn(0.0f);
        svt[col * PV_PITCH + row] = __float2half_rn(0.0f);
    }
    __syncthreads();

    unsigned sq_u = smem_u32(sq), sk_u = smem_u32(sk);
    unsigned svt_u = smem_u32(svt), sp_u = smem_u32(sP);
    int m0 = wid * 16;

    // ---- S = q @ k^T ----
    {
        float acc[8][4];
        #pragma unroll
        for (int a = 0; a < 8; ++a)
            #pragma unroll
            for (int c = 0; c < 4; ++c) acc[a][c] = 0.0f;

        #pragma unroll
        for (int kt = 0; kt < 2; ++kt) {
            unsigned ah[4];
            LDSM4(ah, sq_u + ((m0 + (lane & 15)) * QK_PITCH + kt * 16 + (lane >> 4) * 8) * 2);
            #pragma unroll
            for (int nt = 0; nt < 4; ++nt) {
                unsigned bh[4];
                LDSM4(bh, sk_u + ((nt * 16 + (lane & 15)) * QK_PITCH + kt * 16 + (lane >> 4) * 8) * 2);
                MMA_F16(acc[nt * 2 + 0], ah, bh[0], bh[2]);
                MMA_F16(acc[nt * 2 + 1], ah, bh[1], bh[3]);
            }
        }
        int r = lane >> 2, c = (lane & 3) * 2;
        #pragma unroll
        for (int nj = 0; nj < 8; ++nj) {
            int j0 = nj * 8 + c;
            sS[(m0 + r) * S_PITCH + j0]     = acc[nj][0];
            sS[(m0 + r) * S_PITCH + j0 + 1] = acc[nj][1];
            sS[(m0 + r + 8) * S_PITCH + j0]     = acc[nj][2];
            sS[(m0 + r + 8) * S_PITCH + j0 + 1] = acc[nj][3];
        }
    }
    __syncthreads();

    // ---- softmax(S + bias) -> P (fp16, cols>=49 zero) ----
    const float* bh_row = bmat + (size_t)h * (NWIN * NWIN);
    for (int i = wid; i < NWIN; i += 4) {
        float v1 = sS[i * S_PITCH + lane] + bh_row[i * NWIN + lane];
        bool ok2 = (lane + 32) < NWIN;
        float v2 = ok2 ? (sS[i * S_PITCH + lane + 32] + bh_row[i * NWIN + lane + 32]) : -1e30f;
        float m = fmaxf(v1, v2);
        #pragma unroll
        for (int o = 16; o; o >>= 1) m = fmaxf(m, __shfl_xor_sync(0xffffffffu, m, o));
        float e1 = __expf(v1 - m);
        float e2 = ok2 ? __expf(v2 - m) : 0.0f;
        float s = e1 + e2;
        #pragma unroll
        for (int o = 16; o; o >>= 1) s += __shfl_xor_sync(0xffffffffu, s, o);
        float inv = 1.0f / s;
        sP[i * PV_PITCH + lane] = __float2half_rn(e1 * inv);
        sP[i * PV_PITCH + lane + 32] = __float2half_rn(ok2 ? e2 * inv : 0.0f);
    }
    __syncthreads();

    // ---- O = P @ V ----
    {
        float acc[4][4];
        #pragma unroll
        for (int a = 0; a < 4; ++a)
            #pragma unroll
            for (int c = 0; c < 4; ++c) acc[a][c] = 0.0f;

        #pragma unroll
        for (int kt = 0; kt < 4; ++kt) {
            unsigned ah[4];
            LDSM4(ah, sp_u + ((m0 + (lane & 15)) * PV_PITCH + kt * 16 + (lane >> 4) * 8) * 2);
            #pragma unroll
            for (int nt = 0; nt < 2; ++nt) {
                unsigned bh[4];
                LDSM4(bh, svt_u + ((nt * 16 + (lane & 15)) * PV_PITCH + kt * 16 + (lane >> 4) * 8) * 2);
                MMA_F16(acc[nt * 2 + 0], ah, bh[0], bh[2]);
                MMA_F16(acc[nt * 2 + 1], ah, bh[1], bh[3]);
            }
        }
        int r = lane >> 2, c = (lane & 3) * 2;
        int i0 = m0 + r;
        #pragma unroll
        for (int nt = 0; nt < 4; ++nt) {
            int d = nt * 8 + c;
            if (i0 < NWIN) {
                __half2 hp;
                hp.x = __float2half_rn(acc[nt][0]); hp.y = __float2half_rn(acc[nt][1]);
                *(__half2*)&ao[((size_t)w * NWIN + i0) * CDIM + h * HDIM + d] = hp;
            }
            if (i0 + 8 < NWIN) {
                __half2 hp;
                hp.x = __float2half_rn(acc[nt][2]); hp.y = __float2half_rn(acc[nt][3]);
                *(__half2*)&ao[((size_t)w * NWIN + i0 + 8) * CDIM + h * HDIM + d] = hp;
            }
        }
    }
}

// ============================================================
// launch
// ============================================================
extern "C" void kernel_launch(void* const* d_in, const int* in_sizes, int n_in,
                              void* d_out, int out_size)
{
    (void)in_sizes; (void)n_in; (void)out_size;
    const float* x     = (const float*)d_in[0];
    const float* kv    = (const float*)d_in[1];
    const int*   rel   = (const int*)d_in[2];
    const float* g1    = (const float*)d_in[5];
    const float* b1    = (const float*)d_in[6];
    const float* Wqkv  = (const float*)d_in[7];
    const float* bqkv  = (const float*)d_in[8];
    const float* btab  = (const float*)d_in[9];
    const float* Wproj = (const float*)d_in[10];
    const float* bproj = (const float*)d_in[11];
    const float* g2    = (const float*)d_in[12];
    const float* b2    = (const float*)d_in[13];
    const float* Wfc1  = (const float*)d_in[14];
    const float* bfc1  = (const float*)d_in[15];
    const float* Wfc2  = (const float*)d_in[16];
    const float* bfc2  = (const float*)d_in[17];
    float* out = (float*)d_out;

    static float *x1 = nullptr, *bm = nullptr;
    static fp16 *hw, *qh, *ao, *h2, *mid, *wq, *wp, *w1, *w2;
    if (!x1) {
        cudaGetSymbolAddress((void**)&x1,  g_x1);
        cudaGetSymbolAddress((void**)&bm,  g_bmat);
        cudaGetSymbolAddress((void**)&hw,  g_hw);
        cudaGetSymbolAddress((void**)&qh,  g_qh);
        cudaGetSymbolAddress((void**)&ao,  g_ao);
        cudaGetSymbolAddress((void**)&h2,  g_h2);
        cudaGetSymbolAddress((void**)&mid, g_mid);
        cudaGetSymbolAddress((void**)&wq,  g_wq);
        cudaGetSymbolAddress((void**)&wp,  g_wp);
        cudaGetSymbolAddress((void**)&w1,  g_w1);
        cudaGetSymbolAddress((void**)&w2,  g_w2);
        cudaFuncSetAttribute(mma_gemm<EPI_Q>,    cudaFuncAttributeMaxDynamicSharedMemorySize, SMEM_DYN);
        cudaFuncSetAttribute(mma_gemm<EPI_PROJ>, cudaFuncAttributeMaxDynamicSharedMemorySize, SMEM_DYN);
        cudaFuncSetAttribute(mma_gemm<EPI_GELU>, cudaFuncAttributeMaxDynamicSharedMemorySize, SMEM_DYN);
        cudaFuncSetAttribute(mma_gemm<EPI_FC2>,  cudaFuncAttributeMaxDynamicSharedMemorySize, SMEM_DYN);
    }

    const float qscale = 0.17677669529663687f;

    conv_all<<<5760, 256>>>(Wqkv, Wproj, Wfc1, Wfc2, wq, wp, w1, w2);
    bias_mat<<<(NHEADS * NWIN * NWIN + 255) / 256, 256>>>(rel, btab, bm);

    ln_kernel<<<MROWS, 128>>>(x, g1, b1, hw, 1);

    mma_gemm<EPI_Q><<<dim3(3, 392), 256, SMEM_DYN>>>(hw, wq, 384,
        bqkv, nullptr, qh, nullptr, qscale);

    attn_tc<<<BWIN * NHEADS, 128>>>(qh, kv, bm, ao);

    mma_gemm<EPI_PROJ><<<dim3(3, 392), 256, SMEM_DYN>>>(ao, wp, 384,
        bproj, x1, nullptr, x, 0.0f);

    ln_kernel<<<MROWS, 128>>>(x1, g2, b2, h2, 0);

    mma_gemm<EPI_GELU><<<dim3(12, 392), 256, SMEM_DYN>>>(h2, w1, 384,
        bfc1, nullptr, mid, nullptr, 0.0f);

    mma_gemm<EPI_FC2><<<dim3(3, 392), 256, SMEM_DYN>>>(mid, w2, 1536,
        bfc2, out, nullptr, x1, 0.0f);
}

// round 6
// speedup vs baseline: 5.0944x; 1.0261x over previous
#include <cuda_runtime.h>
#include <cuda_fp16.h>
#include <math.h>

// Problem constants
#define MROWS  50176
#define CDIM   384
#define HIDDEN 1536
#define NHEADS 12
#define HDIM   32
#define NWIN   49
#define BWIN   1024

typedef __half fp16;

// -------- scratch (device globals; no allocations allowed) --------
__device__ float g_x1[(size_t)MROWS * CDIM];
__device__ fp16 g_hw [(size_t)MROWS * CDIM];
__device__ fp16 g_qh [(size_t)MROWS * CDIM];
__device__ fp16 g_ao [(size_t)MROWS * CDIM];
__device__ fp16 g_h2 [(size_t)MROWS * CDIM];
__device__ fp16 g_mid[(size_t)MROWS * HIDDEN];
__device__ fp16 g_wq [384 * 384];
__device__ fp16 g_wp [384 * 384];
__device__ fp16 g_w1 [384 * 1536];
__device__ fp16 g_w2 [1536 * 384];
__device__ fp16 g_kvh[2 * 16 * NHEADS * NWIN * HDIM];
__device__ float g_bmat[NHEADS * NWIN * NWIN];

// ================= PTX helpers =================
__device__ __forceinline__ unsigned smem_u32(const void* p) {
    unsigned a;
    asm("{ .reg .u64 t; cvta.to.shared.u64 t, %1; cvt.u32.u64 %0, t; }" : "=r"(a) : "l"(p));
    return a;
}
__device__ __forceinline__ void cp16(unsigned dst, const void* src) {
    asm volatile("cp.async.cg.shared.global [%0], [%1], 16;" :: "r"(dst), "l"(src) : "memory");
}
#define CP_COMMIT() asm volatile("cp.async.commit_group;" ::: "memory")
#define CP_WAIT(n)  asm volatile("cp.async.wait_group %0;" :: "n"(n) : "memory")

#define LDSM4(r, a)                                                                \
    asm volatile("ldmatrix.sync.aligned.m8n8.x4.shared.b16 {%0,%1,%2,%3}, [%4];"   \
        : "=r"((r)[0]), "=r"((r)[1]), "=r"((r)[2]), "=r"((r)[3]) : "r"(a))

#define MMA_F16(d, a, b0, b1)                                                      \
    asm volatile("mma.sync.aligned.m16n8k16.row.col.f32.f16.f16.f32 "              \
        "{%0,%1,%2,%3}, {%4,%5,%6,%7}, {%8,%9}, {%0,%1,%2,%3};"                    \
        : "+f"((d)[0]), "+f"((d)[1]), "+f"((d)[2]), "+f"((d)[3])                    \
        : "r"((a)[0]), "r"((a)[1]), "r"((a)[2]), "r"((a)[3]), "r"(b0), "r"(b1))

// ============================================================
// Fused weight + kv conversions (one launch)
// W (Kd x Nd, lead ld) -> fp16 (Nd x Kd row-major); kv fp32->fp16
// ============================================================
__global__ void conv_all(const float* __restrict__ Wq, const float* __restrict__ Wp,
                         const float* __restrict__ W1, const float* __restrict__ W2,
                         const float* __restrict__ kv,
                         fp16* __restrict__ oq, fp16* __restrict__ op,
                         fp16* __restrict__ o1, fp16* __restrict__ o2,
                         fp16* __restrict__ okv)
{
    int b = blockIdx.x;
    if (b >= 5760) {  // kv convert: 1204224 elems = 4704 blocks
        int idx = (b - 5760) * 256 + threadIdx.x;
        if (idx < 2 * 16 * NHEADS * NWIN * HDIM)
            okv[idx] = __float2half_rn(kv[idx]);
        return;
    }
    const float* W; fp16* o; int Kd, Nd, ld, base;
    if (b < 576)        { W = Wq; o = oq; Kd = 384;  Nd = 384;  ld = 1152; base = 0; }
    else if (b < 1152)  { W = Wp; o = op; Kd = 384;  Nd = 384;  ld = 384;  base = 576; }
    else if (b < 3456)  { W = W1; o = o1; Kd = 384;  Nd = 1536; ld = 1536; base = 1152; }
    else                { W = W2; o = o2; Kd = 1536; Nd = 384;  ld = 384;  base = 3456; }
    int idx = (b - base) * 256 + threadIdx.x;
    if (idx >= Kd * Nd) return;
    int k = idx / Nd, n = idx - k * Nd;
    o[(size_t)n * Kd + k] = __float2half_rn(W[(size_t)k * ld + n]);
}

// ============================================================
// bias matrix precompute
// ============================================================
__global__ void bias_mat(const int* __restrict__ rel, const float* __restrict__ btab,
                         float* __restrict__ bm)
{
    int t = blockIdx.x * 256 + threadIdx.x;
    if (t >= NHEADS * NWIN * NWIN) return;
    int h = t / (NWIN * NWIN), ij = t % (NWIN * NWIN);
    bm[t] = btab[rel[ij] * NHEADS + h];
}

// ============================================================
// LayerNorm -> fp16
// ============================================================
__global__ void ln_kernel(const float* __restrict__ xin, const float* __restrict__ g,
                          const float* __restrict__ bb, fp16* __restrict__ oh,
                          int windowed)
{
    int r = blockIdx.x;
    size_t srow;
    if (windowed) {
        int w = r / NWIN, n = r % NWIN;
        int bimg = w >> 6, wy = (w >> 3) & 7, wx = w & 7;
        int iy = n / 7, ix = n % 7;
        srow = (size_t)bimg * 3136 + (wy * 7 + iy) * 56 + (wx * 7 + ix);
    } else srow = (size_t)r;
    const float* xr = xin + srow * CDIM;
    int tid = threadIdx.x;
    float v0 = xr[tid], v1 = xr[tid + 128], v2 = xr[tid + 256];
    float s = v0 + v1 + v2, ss = v0 * v0 + v1 * v1 + v2 * v2;
    #pragma unroll
    for (int o = 16; o; o >>= 1) {
        s  += __shfl_xor_sync(0xffffffffu, s,  o);
        ss += __shfl_xor_sync(0xffffffffu, ss, o);
    }
    __shared__ float rs[4], rss[4], smean, sinv;
    int warp = tid >> 5, lane = tid & 31;
    if (lane == 0) { rs[warp] = s; rss[warp] = ss; }
    __syncthreads();
    if (tid == 0) {
        float S = rs[0] + rs[1] + rs[2] + rs[3];
        float SS = rss[0] + rss[1] + rss[2] + rss[3];
        float m = S * (1.0f / 384.0f);
        smean = m;
        sinv = rsqrtf(SS * (1.0f / 384.0f) - m * m + 1e-5f);
    }
    __syncthreads();
    size_t orow = (size_t)r * CDIM;
    #pragma unroll
    for (int c = 0; c < 3; ++c) {
        float vv = (c == 0 ? v0 : c == 1 ? v1 : v2);
        int col = tid + c * 128;
        oh[orow + col] = __float2half_rn((vv - smean) * sinv * g[col] + bb[col]);
    }
}

// ============================================================
// fp16 tensor-core GEMM, 128x128 tile, KC=32, 4-stage cp.async
// pipeline, one barrier per K-iteration.
// ============================================================
enum { EPI_Q = 0, EPI_PROJ = 1, EPI_GELU = 2, EPI_FC2 = 3 };
#define TILE_B   10240
#define STAGE_B  20480
#define NSTAGE   4
#define SMEM_DYN (NSTAGE * STAGE_B)   // 81920

template <int EPI>
__global__ void __launch_bounds__(256, 2)
mma_gemm(const fp16* __restrict__ Am, const fp16* __restrict__ Bm,
         int K, const float* __restrict__ bias,
         float* __restrict__ Cf, fp16* __restrict__ Ch,
         const float* __restrict__ resid, float scale)
{
    extern __shared__ char sm_raw[];
    unsigned sbase = smem_u32(sm_raw);

    int tid = threadIdx.x, wid = tid >> 5, lane = tid & 31;
    int bm = blockIdx.y * 128, bn = blockIdx.x * 128;
    int m0 = (wid & 3) * 32, n0 = (wid >> 2) * 64;

    int rowL[4], chL[4], tileL[4];
    #pragma unroll
    for (int t = 0; t < 4; ++t) {
        int item = tid + t * 256;
        tileL[t] = item >> 9;
        int rem = item & 511;
        rowL[t] = rem >> 2; chL[t] = rem & 3;
    }

    auto load_stage = [&](int stage, int k0) {
        unsigned db = sbase + stage * STAGE_B;
        #pragma unroll
        for (int t = 0; t < 4; ++t) {
            const fp16* src = (tileL[t] ? Bm : Am)
                + (size_t)((tileL[t] ? bn : bm) + rowL[t]) * K + k0 + chL[t] * 8;
            cp16(db + tileL[t] * TILE_B + rowL[t] * 80 + chL[t] * 16, src);
        }
        CP_COMMIT();
    };

    float acc[2][8][4];
    #pragma unroll
    for (int a = 0; a < 2; ++a)
        #pragma unroll
        for (int b = 0; b < 8; ++b)
            #pragma unroll
            for (int c = 0; c < 4; ++c) acc[a][b][c] = 0.0f;

    int niter = K >> 5;          // >= 12 always here
    load_stage(0, 0);
    load_stage(1, 32);
    load_stage(2, 64);

    for (int it = 0; it < niter; ++it) {
        CP_WAIT(2);              // stage it resident (3+it commits, ≤2 outstanding)
        __syncthreads();

        // prefetch stage it+3 (overwrites stage it-1: reads done pre-barrier)
        if (it + 3 < niter) load_stage((it + 3) & 3, (it + 3) * 32);
        else CP_COMMIT();        // keep group count uniform

        unsigned base = sbase + (it & 3) * STAGE_B;
        #pragma unroll
        for (int ks = 0; ks < 2; ++ks) {
            unsigned ah[2][4];
            #pragma unroll
            for (int mt = 0; mt < 2; ++mt) {
                unsigned ra = base + (m0 + mt * 16 + (lane & 15)) * 80
                            + (ks * 2 + (lane >> 4)) * 16;
                LDSM4(ah[mt], ra);
            }
            #pragma unroll
            for (int nt = 0; nt < 4; ++nt) {
                unsigned rb = base + TILE_B + (n0 + nt * 16 + (lane & 15)) * 80
                            + (ks * 2 + (lane >> 4)) * 16;
                unsigned bh[4];
                LDSM4(bh, rb);
                #pragma unroll
                for (int mt = 0; mt < 2; ++mt) {
                    MMA_F16(acc[mt][nt * 2 + 0], ah[mt], bh[0], bh[2]);
                    MMA_F16(acc[mt][nt * 2 + 1], ah[mt], bh[1], bh[3]);
                }
            }
        }
    }

    int r_in = lane >> 2, c_in = (lane & 3) * 2;
    #pragma unroll
    for (int mt = 0; mt < 2; ++mt) {
        #pragma unroll
        for (int j = 0; j < 8; ++j) {
            int col = bn + n0 + j * 8 + c_in;
            #pragma unroll
            for (int hf = 0; hf < 2; ++hf) {
                int row = bm + m0 + mt * 16 + r_in + hf * 8;
                float v0 = acc[mt][j][hf * 2 + 0];
                float v1 = acc[mt][j][hf * 2 + 1];
                if (EPI == EPI_Q) {
                    int w = row / NWIN, n = row % NWIN;
                    int hd = col >> 5, d = col & 31;
                    __half2 hp;
                    hp.x = __float2half_rn((v0 + bias[col]) * scale);
                    hp.y = __float2half_rn((v1 + bias[col + 1]) * scale);
                    *(__half2*)&Ch[((size_t)(w * NHEADS + hd) * NWIN + n) * HDIM + d] = hp;
                } else if (EPI == EPI_PROJ) {
                    int w = row / NWIN, n = row % NWIN;
                    int bimg = w >> 6, wy = (w >> 3) & 7, wx = w & 7;
                    int iy = n / 7, ix = n % 7;
                    size_t o = ((size_t)bimg * 3136 + (wy * 7 + iy) * 56 + (wx * 7 + ix)) * CDIM + col;
                    float2 r2 = *(const float2*)&resid[o];
                    *(float2*)&Cf[o] = make_float2(v0 + bias[col] + r2.x,
                                                   v1 + bias[col + 1] + r2.y);
                } else if (EPI == EPI_GELU) {
                    float a0 = v0 + bias[col], a1 = v1 + bias[col + 1];
                    float g0 = 0.5f * a0 * (1.0f + erff(a0 * 0.70710678118654752f));
                    float g1 = 0.5f * a1 * (1.0f + erff(a1 * 0.70710678118654752f));
                    __half2 hp;
                    hp.x = __float2half_rn(g0); hp.y = __float2half_rn(g1);
                    *(__half2*)&Ch[(size_t)row * HIDDEN + col] = hp;
                } else {
                    size_t o = (size_t)row * CDIM + col;
                    float2 r2 = *(const float2*)&resid[o];
                    *(float2*)&Cf[o] = make_float2(v0 + bias[col] + r2.x,
                                                   v1 + bias[col + 1] + r2.y);
                }
            }
        }
    }
}

// ============================================================
// Tensor-core windowed attention (kv pre-converted to fp16)
// ============================================================
#define QK_PITCH 40
#define PV_PITCH 72
#define S_PITCH  66

__global__ void __launch_bounds__(128)
attn_tc(const fp16* __restrict__ q, const fp16* __restrict__ kvh,
        const float* __restrict__ bmat, fp16* __restrict__ ao)
{
    __shared__ fp16 sq [64 * QK_PITCH];
    __shared__ fp16 sk [64 * QK_PITCH];
    __shared__ fp16 svt[32 * PV_PITCH];
    __shared__ float sS[64 * S_PITCH];
    __shared__ fp16 sP [64 * PV_PITCH];

    int blk = blockIdx.x;
    int w = blk / NHEADS, h = blk - w * NHEADS;
    int bimg = w >> 6;
    int tid = threadIdx.x, wid = tid >> 5, lane = tid & 31;

    const fp16* qp = q + (size_t)blk * (NWIN * HDIM);
    const fp16* kp = kvh + (size_t)(bimg * NHEADS + h) * (NWIN * HDIM);
    const fp16* vp = kp + (size_t)16 * NHEADS * NWIN * HDIM;

    // q, k: 196 uint4 each (vectorized)
    for (int t = tid; t < 196; t += 128) {
        int row = t >> 2, col = (t & 3) * 8;
        *(uint4*)&sq[row * QK_PITCH + col] = ((const uint4*)qp)[t];
        *(uint4*)&sk[row * QK_PITCH + col] = ((const uint4*)kp)[t];
    }
    for (int t = tid; t < 60; t += 128) {
        int row = 49 + (t >> 2), col = (t & 3) * 8;
        *(uint4*)&sq[row * QK_PITCH + col] = make_uint4(0, 0, 0, 0);
        *(uint4*)&sk[row * QK_PITCH + col] = make_uint4(0, 0, 0, 0);
    }
    // v -> transposed
    for (int t = tid; t < NWIN * HDIM; t += 128) {
        int row = t >> 5, col = t & 31;
        svt[col * PV_PITCH + row] = vp[t];
    }
    for (int t = tid; t < 480; t += 128) {
        int row = 49 + (t >> 5), col = t & 31;
        svt[col * PV_PITCH + row] = __float2half_rn(0.0f);
    }
    __syncthreads();

    unsigned sq_u = smem_u32(sq), sk_u = smem_u32(sk);
    unsigned svt_u = smem_u32(svt), sp_u = smem_u32(sP);
    int m0 = wid * 16;

    // ---- S = q @ k^T ----
    {
        float acc[8][4];
        #pragma unroll
        for (int a = 0; a < 8; ++a)
            #pragma unroll
            for (int c = 0; c < 4; ++c) acc[a][c] = 0.0f;

        #pragma unroll
        for (int kt = 0; kt < 2; ++kt) {
            unsigned ah[4];
            LDSM4(ah, sq_u + ((m0 + (lane & 15)) * QK_PITCH + kt * 16 + (lane >> 4) * 8) * 2);
            #pragma unroll
            for (int nt = 0; nt < 4; ++nt) {
                unsigned bh[4];
                LDSM4(bh, sk_u + ((nt * 16 + (lane & 15)) * QK_PITCH + kt * 16 + (lane >> 4) * 8) * 2);
                MMA_F16(acc[nt * 2 + 0], ah, bh[0], bh[2]);
                MMA_F16(acc[nt * 2 + 1], ah, bh[1], bh[3]);
            }
        }
        int r = lane >> 2, c = (lane & 3) * 2;
        #pragma unroll
        for (int nj = 0; nj < 8; ++nj) {
            int j0 = nj * 8 + c;
            sS[(m0 + r) * S_PITCH + j0]     = acc[nj][0];
            sS[(m0 + r) * S_PITCH + j0 + 1] = acc[nj][1];
            sS[(m0 + r + 8) * S_PITCH + j0]     = acc[nj][2];
            sS[(m0 + r + 8) * S_PITCH + j0 + 1] = acc[nj][3];
        }
    }
    __syncthreads();

    // ---- softmax(S + bias) -> P ----
    const float* bh_row = bmat + (size_t)h * (NWIN * NWIN);
    for (int i = wid; i < NWIN; i += 4) {
        float v1 = sS[i * S_PITCH + lane] + bh_row[i * NWIN + lane];
        bool ok2 = (lane + 32) < NWIN;
        float v2 = ok2 ? (sS[i * S_PITCH + lane + 32] + bh_row[i * NWIN + lane + 32]) : -1e30f;
        float m = fmaxf(v1, v2);
        #pragma unroll
        for (int o = 16; o; o >>= 1) m = fmaxf(m, __shfl_xor_sync(0xffffffffu, m, o));
        float e1 = __expf(v1 - m);
        float e2 = ok2 ? __expf(v2 - m) : 0.0f;
        float s = e1 + e2;
        #pragma unroll
        for (int o = 16; o; o >>= 1) s += __shfl_xor_sync(0xffffffffu, s, o);
        float inv = 1.0f / s;
        sP[i * PV_PITCH + lane] = __float2half_rn(e1 * inv);
        sP[i * PV_PITCH + lane + 32] = __float2half_rn(ok2 ? e2 * inv : 0.0f);
    }
    __syncthreads();

    // ---- O = P @ V ----
    {
        float acc[4][4];
        #pragma unroll
        for (int a = 0; a < 4; ++a)
            #pragma unroll
            for (int c = 0; c < 4; ++c) acc[a][c] = 0.0f;

        #pragma unroll
        for (int kt = 0; kt < 4; ++kt) {
            unsigned ah[4];
            LDSM4(ah, sp_u + ((m0 + (lane & 15)) * PV_PITCH + kt * 16 + (lane >> 4) * 8) * 2);
            #pragma unroll
            for (int nt = 0; nt < 2; ++nt) {
                unsigned bh[4];
                LDSM4(bh, svt_u + ((nt * 16 + (lane & 15)) * PV_PITCH + kt * 16 + (lane >> 4) * 8) * 2);
                MMA_F16(acc[nt * 2 + 0], ah, bh[0], bh[2]);
                MMA_F16(acc[nt * 2 + 1], ah, bh[1], bh[3]);
            }
        }
        int r = lane >> 2, c = (lane & 3) * 2;
        int i0 = m0 + r;
        #pragma unroll
        for (int nt = 0; nt < 4; ++nt) {
            int d = nt * 8 + c;
            if (i0 < NWIN) {
                __half2 hp;
                hp.x = __float2half_rn(acc[nt][0]); hp.y = __float2half_rn(acc[nt][1]);
                *(__half2*)&ao[((size_t)w * NWIN + i0) * CDIM + h * HDIM + d] = hp;
            }
            if (i0 + 8 < NWIN) {
                __half2 hp;
                hp.x = __float2half_rn(acc[nt][2]); hp.y = __float2half_rn(acc[nt][3]);
                *(__half2*)&ao[((size_t)w * NWIN + i0 + 8) * CDIM + h * HDIM + d] = hp;
            }
        }
    }
}

// ============================================================
// launch
// ============================================================
extern "C" void kernel_launch(void* const* d_in, const int* in_sizes, int n_in,
                              void* d_out, int out_size)
{
    (void)in_sizes; (void)n_in; (void)out_size;
    const float* x     = (const float*)d_in[0];
    const float* kv    = (const float*)d_in[1];
    const int*   rel   = (const int*)d_in[2];
    const float* g1    = (const float*)d_in[5];
    const float* b1    = (const float*)d_in[6];
    const float* Wqkv  = (const float*)d_in[7];
    const float* bqkv  = (const float*)d_in[8];
    const float* btab  = (const float*)d_in[9];
    const float* Wproj = (const float*)d_in[10];
    const float* bproj = (const float*)d_in[11];
    const float* g2    = (const float*)d_in[12];
    const float* b2    = (const float*)d_in[13];
    const float* Wfc1  = (const float*)d_in[14];
    const float* bfc1  = (const float*)d_in[15];
    const float* Wfc2  = (const float*)d_in[16];
    const float* bfc2  = (const float*)d_in[17];
    float* out = (float*)d_out;

    static float *x1 = nullptr, *bm = nullptr;
    static fp16 *hw, *qh, *ao, *h2, *mid, *wq, *wp, *w1, *w2, *kvh;
    if (!x1) {
        cudaGetSymbolAddress((void**)&x1,  g_x1);
        cudaGetSymbolAddress((void**)&bm,  g_bmat);
        cudaGetSymbolAddress((void**)&hw,  g_hw);
        cudaGetSymbolAddress((void**)&qh,  g_qh);
        cudaGetSymbolAddress((void**)&ao,  g_ao);
        cudaGetSymbolAddress((void**)&h2,  g_h2);
        cudaGetSymbolAddress((void**)&mid, g_mid);
        cudaGetSymbolAddress((void**)&wq,  g_wq);
        cudaGetSymbolAddress((void**)&wp,  g_wp);
        cudaGetSymbolAddress((void**)&w1,  g_w1);
        cudaGetSymbolAddress((void**)&w2,  g_w2);
        cudaGetSymbolAddress((void**)&kvh, g_kvh);
        cudaFuncSetAttribute(mma_gemm<EPI_Q>,    cudaFuncAttributeMaxDynamicSharedMemorySize, SMEM_DYN);
        cudaFuncSetAttribute(mma_gemm<EPI_PROJ>, cudaFuncAttributeMaxDynamicSharedMemorySize, SMEM_DYN);
        cudaFuncSetAttribute(mma_gemm<EPI_GELU>, cudaFuncAttributeMaxDynamicSharedMemorySize, SMEM_DYN);
        cudaFuncSetAttribute(mma_gemm<EPI_FC2>,  cudaFuncAttributeMaxDynamicSharedMemorySize, SMEM_DYN);
    }

    const float qscale = 0.17677669529663687f;

    conv_all<<<5760 + 4704, 256>>>(Wqkv, Wproj, Wfc1, Wfc2, kv, wq, wp, w1, w2, kvh);
    bias_mat<<<(NHEADS * NWIN * NWIN + 255) / 256, 256>>>(rel, btab, bm);

    ln_kernel<<<MROWS, 128>>>(x, g1, b1, hw, 1);

    mma_gemm<EPI_Q><<<dim3(3, 392), 256, SMEM_DYN>>>(hw, wq, 384,
        bqkv, nullptr, qh, nullptr, qscale);

    attn_tc<<<BWIN * NHEADS, 128>>>(qh, kvh, bm, ao);

    mma_gemm<EPI_PROJ><<<dim3(3, 392), 256, SMEM_DYN>>>(ao, wp, 384,
        bproj, x1, nullptr, x, 0.0f);

    ln_kernel<<<MROWS, 128>>>(x1, g2, b2, h2, 0);

    mma_gemm<EPI_GELU><<<dim3(12, 392), 256, SMEM_DYN>>>(h2, w1, 384,
        bfc1, nullptr, mid, nullptr, 0.0f);

    mma_gemm<EPI_FC2><<<dim3(3, 392), 256, SMEM_DYN>>>(mid, w2, 1536,
        bfc2, out, nullptr, x1, 0.0f);
}